// round 1
// baseline (speedup 1.0000x reference)
#include <cuda_runtime.h>
#include <math.h>

#define BATCH 8
#define HP 256        // pooled H/W
#define HF 512        // full H/W

// Scratch (device globals — no allocation allowed)
__device__ float g_pool[4][BATCH][HP][HP];        // 0=fixed,1=moved,2=u,3=v (8MB)
__device__ float g_diff[BATCH * 8][HP][HP];       // mind descriptor diff (16MB)
__device__ unsigned int g_hist[BATCH][256];
__device__ float g_part_mind[32768];
__device__ float g_part_reg[2048];
__device__ float g_scalars[3];                    // 0 mind_sum, 1 mi_loss, 2 reg_sum

__device__ __forceinline__ float san(float v) { return (v == v) ? v : 0.0f; }
__device__ __forceinline__ int clampi(int v, int lo, int hi) { return min(max(v, lo), hi); }

// ---------------- zero histograms ----------------
__global__ void k_zero() {
    int i = blockIdx.x * blockDim.x + threadIdx.x;
    if (i < BATCH * 256) ((unsigned int*)g_hist)[i] = 0u;
}

// ---------------- 2x2 avg pool for fixed, moved, flow_u, flow_v ----------------
__global__ void k_pool(const float* __restrict__ fixed,
                       const float* __restrict__ moved,
                       const float* __restrict__ flow) {
    int idx = blockIdx.x * blockDim.x + threadIdx.x;
    if (idx >= 4 * BATCH * HP * HP) return;
    int x = idx & (HP - 1);
    int y = (idx >> 8) & (HP - 1);
    int b = (idx >> 16) & 7;
    int p = idx >> 19;
    const float* src;
    if (p == 0)      src = fixed + (size_t)b * HF * HF;
    else if (p == 1) src = moved + (size_t)b * HF * HF;
    else             src = flow + ((size_t)b * 2 + (p - 2)) * HF * HF;
    const float* r0 = src + (size_t)(2 * y) * HF + 2 * x;
    float s = san(r0[0]) + san(r0[1]) + san(r0[HF]) + san(r0[HF + 1]);
    g_pool[p][b][y][x] = 0.25f * s;
}

// ---------------- MIND descriptors for both images, write diff ----------------
#define BX 32
#define BY 16
__global__ __launch_bounds__(512) void k_mind() {
    __shared__ float sF[BY + 6][BX + 6];
    __shared__ float sM[BY + 6][BX + 6];
    __shared__ float vF[BY + 2][BX + 2];
    __shared__ float vM[BY + 2][BX + 2];

    int b = blockIdx.z;
    int tileX = blockIdx.x * BX, tileY = blockIdx.y * BY;
    int gx0 = tileX - 3, gy0 = tileY - 3;
    int tid = threadIdx.y * BX + threadIdx.x;
    const float* imF = &g_pool[0][b][0][0];
    const float* imM = &g_pool[1][b][0][0];

    for (int s = tid; s < (BY + 6) * (BX + 6); s += 512) {
        int sy = s / (BX + 6), sx = s % (BX + 6);
        int gy = clampi(gy0 + sy, 0, HP - 1);
        int gx = clampi(gx0 + sx, 0, HP - 1);
        sF[sy][sx] = imF[gy * HP + gx];
        sM[sy][sx] = imM[gy * HP + gx];
    }
    __syncthreads();

    // variance_pre (vp) at pixel + 1 halo. Reference quirk: patch mean taps are
    // img[clamp(u-2+s)] for s in {0,1,2}  (box centered at u-1).
    for (int s = tid; s < (BY + 2) * (BX + 2); s += 512) {
        int sy = s / (BX + 2), sx = s % (BX + 2);
        int uc = clampi(tileY - 1 + sy, 0, HP - 1);
        int vc = clampi(tileX - 1 + sx, 0, HP - 1);
        float pmF = 0.f, pmM = 0.f;
        #pragma unroll
        for (int a = 0; a < 3; a++) {
            int rr = clampi(uc - 2 + a, 0, HP - 1) - gy0;
            #pragma unroll
            for (int bb = 0; bb < 3; bb++) {
                int cc = clampi(vc - 2 + bb, 0, HP - 1) - gx0;
                pmF += sF[rr][cc];
                pmM += sM[rr][cc];
            }
        }
        float cF = sF[uc - gy0][vc - gx0];
        float cM = sM[uc - gy0][vc - gx0];
        float dF = cF - pmF * (1.0f / 9.0f);
        float dM = cM - pmM * (1.0f / 9.0f);
        vF[sy][sx] = dF * dF;
        vM[sy][sx] = dM * dM;
    }
    __syncthreads();

    int y = tileY + threadIdx.y;
    int x = tileX + threadIdx.x;

    float vsF = 0.f, vsM = 0.f;
    #pragma unroll
    for (int a = -1; a <= 1; a++) {
        int rr = clampi(y + a, 0, HP - 1) - (tileY - 1);
        #pragma unroll
        for (int bb = -1; bb <= 1; bb++) {
            int cc = clampi(x + bb, 0, HP - 1) - (tileX - 1);
            vsF += vF[rr][cc];
            vsM += vM[rr][cc];
        }
    }
    float varF = fmaxf(vsF * (1.0f / 9.0f), 1e-4f);
    float varM = fmaxf(vsM * (1.0f / 9.0f), 1e-4f);
    float invF = 1.0f / (varF * 2.0f + 1e-6f);
    float invM = 1.0f / (varM * 2.0f + 1e-6f);
    float cF = sF[y - gy0][x - gx0];
    float cM = sM[y - gy0][x - gx0];

    // channel order: (i outer -> dx, j inner -> dy), skip (0,0)
    const int offdx[8] = {-2, -2, -2, 0, 0, 2, 2, 2};
    const int offdy[8] = {-2, 0, 2, -2, 2, -2, 0, 2};
    float eF[8], eM[8];
    float sumF = 0.f, sumM = 0.f;
    #pragma unroll
    for (int c = 0; c < 8; c++) {
        int rr = clampi(y + offdy[c], 0, HP - 1) - gy0;
        int cc = clampi(x + offdx[c], 0, HP - 1) - gx0;
        float oF = sF[rr][cc], oM = sM[rr][cc];
        float dfF = cF - oF, dfM = cM - oM;
        float qF = fminf(dfF * dfF * invF, 50.0f);
        float qM = fminf(dfM * dfM * invM, 50.0f);
        eF[c] = __expf(-qF);
        eM[c] = __expf(-qM);
        sumF += eF[c];
        sumM += eM[c];
    }
    float rF = 1.0f / (sumF + 1e-8f), rM = 1.0f / (sumM + 1e-8f);
    #pragma unroll
    for (int c = 0; c < 8; c++) {
        g_diff[b * 8 + c][y][x] = eF[c] * rF - eM[c] * rM;
    }
}

// ---------------- bilinear upsample (align corners) of diff, |.| partial sums ----
__global__ __launch_bounds__(256) void k_up() {
    const float SCALE = 255.0f / 511.0f;   // (n_in-1)/(n_out-1), f32 like JAX
    int blk = blockIdx.x;          // 0..32767 : plane(64) x row(512)
    int plane = blk >> 9;
    int y = blk & 511;
    float pos = (float)y * SCALE;
    int i0 = clampi((int)floorf(pos), 0, HP - 2);
    float fy = pos - (float)i0;
    const float* r0 = &g_diff[plane][i0][0];
    const float* r1 = &g_diff[plane][i0 + 1][0];

    float acc = 0.f;
    #pragma unroll
    for (int k = 0; k < 2; k++) {
        int x = threadIdx.x + k * 256;
        float px = (float)x * SCALE;
        int j0 = clampi((int)floorf(px), 0, HP - 2);
        float fx = px - (float)j0;
        float a = r0[j0], bq = r0[j0 + 1], cq = r1[j0], d = r1[j0 + 1];
        float t0 = a * (1.0f - fy) + cq * fy;
        float t1 = bq * (1.0f - fy) + d * fy;
        acc += fabsf(t0 * (1.0f - fx) + t1 * fx);
    }
    __shared__ float red[256];
    red[threadIdx.x] = acc;
    __syncthreads();
    #pragma unroll
    for (int s = 128; s > 0; s >>= 1) {
        if (threadIdx.x < s) red[threadIdx.x] += red[threadIdx.x + s];
        __syncthreads();
    }
    if (threadIdx.x == 0) g_part_mind[blk] = red[0];
}

// ---------------- joint histogram over [::2,::2] samples ----------------
__global__ __launch_bounds__(512) void k_hist(const float* __restrict__ fixed,
                                              const float* __restrict__ moved) {
    __shared__ unsigned int sh[256];
    if (threadIdx.x < 256) sh[threadIdx.x] = 0u;
    __syncthreads();
    int b = blockIdx.x >> 4;
    int seg = blockIdx.x & 15;
    const float* pf = fixed + (size_t)b * HF * HF;
    const float* pm = moved + (size_t)b * HF * HF;
    for (int i = seg * 4096 + threadIdx.x; i < (seg + 1) * 4096; i += 512) {
        int y = i >> 8, x = i & 255;
        size_t o = (size_t)(2 * y) * HF + 2 * x;
        float xf = san(pf[o]), yf = san(pm[o]);
        xf = fminf(fmaxf((xf + 1.0f) * 0.5f, 0.001f), 0.999f);
        yf = fminf(fmaxf((yf + 1.0f) * 0.5f, 0.001f), 0.999f);
        // searchsorted(linspace(0,1,17), v, 'left') - 1  ==  ceil(v*16)-1 (exact 1/16 grid)
        int xb = clampi((int)ceilf(xf * 16.0f) - 1, 0, 15);
        int yb = clampi((int)ceilf(yf * 16.0f) - 1, 0, 15);
        atomicAdd(&sh[xb * 16 + yb], 1u);
    }
    __syncthreads();
    if (threadIdx.x < 256 && sh[threadIdx.x])
        atomicAdd(&g_hist[b][threadIdx.x], sh[threadIdx.x]);
}

// ---------------- MI / NMI from histograms ----------------
__global__ __launch_bounds__(256) void k_mi() {
    __shared__ float hp[256];
    __shared__ float xh[16], yh[16];
    __shared__ float red[256];
    __shared__ float s_nmi_sum;
    int t = threadIdx.x;
    if (t == 0) s_nmi_sum = 0.f;

    for (int b = 0; b < BATCH; b++) {
        float p = (float)g_hist[b][t] * (1.0f / 65536.0f);
        hp[t] = p;
        __syncthreads();
        if (t < 16) {
            float s = 0.f;
            for (int j = 0; j < 16; j++) s += hp[t * 16 + j];
            xh[t] = s + 1e-5f;
            float s2 = 0.f;
            for (int i2 = 0; i2 < 16; i2++) s2 += hp[i2 * 16 + t];
            yh[t] = s2 + 1e-5f;
        }
        __syncthreads();
        float hpe = p + 1e-5f;
        int i = t >> 4, j = t & 15;
        red[t] = hpe * (logf(hpe) - logf(xh[i] * yh[j]));
        __syncthreads();
        #pragma unroll
        for (int s = 128; s > 0; s >>= 1) {
            if (t < s) red[t] += red[t + s];
            __syncthreads();
        }
        if (t == 0) {
            float mi = red[0];
            float hx = 0.f, hy = 0.f;
            for (int k = 0; k < 16; k++) {
                hx -= xh[k] * logf(xh[k]);
                hy -= yh[k] * logf(yh[k]);
            }
            float se = hx + hy;
            float nmi = (se < 1e-10f) ? 0.0f : 2.0f * mi / se;
            nmi = fminf(fmaxf(nmi, -1.0f), 1.0f);
            s_nmi_sum += nmi;
        }
        __syncthreads();
    }
    if (t == 0) {
        float m = s_nmi_sum * (1.0f / BATCH);
        m = fminf(fmaxf(m, -1.0f), 1.0f);
        g_scalars[1] = -m;
    }
}

// ---------------- regularizer: sobel + laplacian on pooled flow ----------------
__global__ __launch_bounds__(256) void k_reg() {
    int idx = blockIdx.x * 256 + threadIdx.x;
    int x = idx & 255, y = (idx >> 8) & 255, b = idx >> 16;
    const float* u = &g_pool[2][b][0][0];
    const float* v = &g_pool[3][b][0][0];
    int ym = max(y - 1, 0), yp = min(y + 1, 255);
    int xm = max(x - 1, 0), xp = min(x + 1, 255);

    float u00 = u[ym * 256 + xm], u01 = u[ym * 256 + x], u02 = u[ym * 256 + xp];
    float u10 = u[y * 256 + xm],  u11 = u[y * 256 + x],  u12 = u[y * 256 + xp];
    float u20 = u[yp * 256 + xm], u21 = u[yp * 256 + x], u22 = u[yp * 256 + xp];
    float v00 = v[ym * 256 + xm], v01 = v[ym * 256 + x], v02 = v[ym * 256 + xp];
    float v10 = v[y * 256 + xm],  v11 = v[y * 256 + x],  v12 = v[y * 256 + xp];
    float v20 = v[yp * 256 + xm], v21 = v[yp * 256 + x], v22 = v[yp * 256 + xp];

    float gxu = (u02 + 2.f * u12 + u22) - (u00 + 2.f * u10 + u20);
    float gyu = (u20 + 2.f * u21 + u22) - (u00 + 2.f * u01 + u02);
    float lpu = u01 + u10 + u12 + u21 - 4.f * u11;
    float gxv = (v02 + 2.f * v12 + v22) - (v00 + 2.f * v10 + v20);
    float gyv = (v20 + 2.f * v21 + v22) - (v00 + 2.f * v01 + v02);
    float lpv = v01 + v10 + v12 + v21 - 4.f * v11;

    float gm = gxu * gxu + gyu * gyu + gxv * gxv + gyv * gyv;
    float lm = lpu * lpu + lpv * lpv;
    float val = fminf(gm, 100.0f) + fminf(lm, 100.0f);

    __shared__ float red[256];
    red[threadIdx.x] = val;
    __syncthreads();
    #pragma unroll
    for (int s = 128; s > 0; s >>= 1) {
        if (threadIdx.x < s) red[threadIdx.x] += red[threadIdx.x + s];
        __syncthreads();
    }
    if (threadIdx.x == 0) g_part_reg[blockIdx.x] = red[0];
}

// ---------------- deterministic final reductions ----------------
__global__ __launch_bounds__(1024) void k_reduce(int which) {
    const float* src = (which == 0) ? g_part_mind : g_part_reg;
    int n = (which == 0) ? 32768 : 2048;
    float s = 0.f;
    for (int i = threadIdx.x; i < n; i += 1024) s += src[i];
    __shared__ float red[1024];
    red[threadIdx.x] = s;
    __syncthreads();
    #pragma unroll
    for (int st = 512; st > 0; st >>= 1) {
        if (threadIdx.x < st) red[threadIdx.x] += red[threadIdx.x + st];
        __syncthreads();
    }
    if (threadIdx.x == 0) g_scalars[(which == 0) ? 0 : 2] = red[0];
}

__global__ void k_final(float* out) {
    out[0] = g_scalars[1]
           + 5.0f * (g_scalars[0] * (1.0f / 16777216.0f))
           + 0.1f * (g_scalars[2] * (1.0f / 524288.0f));
}

// ---------------- launch ----------------
extern "C" void kernel_launch(void* const* d_in, const int* in_sizes, int n_in,
                              void* d_out, int out_size) {
    // identify flow by size (2 channels); fixed/moved are interchangeable in the math
    const float* fixed = (const float*)d_in[0];
    const float* moved = (const float*)d_in[1];
    const float* flow  = (const float*)d_in[2];
    if (n_in >= 3) {
        // robust: flow has 2x the elements
        int fi = -1;
        for (int i = 0; i < 3; i++) if (in_sizes[i] == 2 * BATCH * HF * HF) fi = i;
        if (fi == 0) { flow = (const float*)d_in[0]; fixed = (const float*)d_in[1]; moved = (const float*)d_in[2]; }
        else if (fi == 1) { fixed = (const float*)d_in[0]; flow = (const float*)d_in[1]; moved = (const float*)d_in[2]; }
        // fi==2: defaults already correct
    }

    k_zero<<<8, 256>>>();
    k_pool<<<(4 * BATCH * HP * HP + 255) / 256, 256>>>(fixed, moved, flow);
    k_mind<<<dim3(HP / BX, HP / BY, BATCH), dim3(BX, BY)>>>();
    k_up<<<32768, 256>>>();
    k_reduce<<<1, 1024>>>(0);
    k_hist<<<128, 512>>>(fixed, moved);
    k_mi<<<1, 256>>>();
    k_reg<<<2048, 256>>>();
    k_reduce<<<1, 1024>>>(1);
    k_final<<<1, 1>>>((float*)d_out);
}

// round 2
// speedup vs baseline: 1.4462x; 1.4462x over previous
#include <cuda_runtime.h>
#include <math.h>

#define BATCH 8
#define HP 256        // pooled H/W
#define HF 512        // full H/W

// Scratch (device globals — no allocation allowed)
__device__ float g_pool[4][BATCH][HP][HP];        // 0=fixed,1=moved,2=u,3=v (8MB)
__device__ float g_diff[BATCH * 8][HP][HP];       // mind descriptor diff (16MB)
__device__ unsigned int g_hist[BATCH][256];
__device__ float g_part_mind[1024];
__device__ float g_part_reg[2048];

__device__ __forceinline__ float san(float v) { return (v == v) ? v : 0.0f; }
__device__ __forceinline__ int clampi(int v, int lo, int hi) { return min(max(v, lo), hi); }

// ---------------- zero histograms ----------------
__global__ void k_zero() {
    int i = blockIdx.x * blockDim.x + threadIdx.x;
    if (i < BATCH * 256) ((unsigned int*)g_hist)[i] = 0u;
}

// ---------- 2x2 avg pool (fixed, moved, u, v) + fused joint histogram ----------
// grid: p(4) x b(8) x strip(16), 256 threads. Each block: 16 pooled rows.
__global__ __launch_bounds__(256) void k_pool(const float* __restrict__ fixed,
                                              const float* __restrict__ moved,
                                              const float* __restrict__ flow) {
    int blk = blockIdx.x;
    int st = blk & 15;
    int b = (blk >> 4) & 7;
    int p = blk >> 7;
    const float* src;
    if (p == 0)      src = fixed + (size_t)b * HF * HF;
    else if (p == 1) src = moved + (size_t)b * HF * HF;
    else             src = flow + ((size_t)b * 2 + (p - 2)) * HF * HF;
    const float* msrc = moved + (size_t)b * HF * HF;

    __shared__ unsigned int sh[256];
    if (p == 0) {
        sh[threadIdx.x] = 0u;
        __syncthreads();
    }

    int x = threadIdx.x;
    for (int r = 0; r < 16; r++) {
        int y = st * 16 + r;
        const float* r0 = src + (size_t)(2 * y) * HF;
        float a = san(r0[2 * x]), bq = san(r0[2 * x + 1]);
        float c = san(r0[HF + 2 * x]), d = san(r0[HF + 2 * x + 1]);
        g_pool[p][b][y][x] = 0.25f * (a + bq + c + d);
        if (p == 0) {
            // joint histogram sample at full-res (2y, 2x): fixed=a, moved below
            float mv = san(msrc[(size_t)(2 * y) * HF + 2 * x]);
            float xf = fminf(fmaxf((a + 1.0f) * 0.5f, 0.001f), 0.999f);
            float yf = fminf(fmaxf((mv + 1.0f) * 0.5f, 0.001f), 0.999f);
            // searchsorted(linspace(0,1,17), v, 'left') - 1 == ceil(v*16)-1 on exact grid
            int xb = clampi((int)ceilf(xf * 16.0f) - 1, 0, 15);
            int yb = clampi((int)ceilf(yf * 16.0f) - 1, 0, 15);
            atomicAdd(&sh[xb * 16 + yb], 1u);
        }
    }
    if (p == 0) {
        __syncthreads();
        unsigned int cnt = sh[threadIdx.x];
        if (cnt) atomicAdd(&g_hist[b][threadIdx.x], cnt);
    }
}

// ---------------- MIND descriptors for both images, write diff ----------------
#define BX 32
#define BY 16
__global__ __launch_bounds__(512) void k_mind() {
    __shared__ float sF[BY + 6][BX + 6];
    __shared__ float sM[BY + 6][BX + 6];
    __shared__ float vF[BY + 2][BX + 2];
    __shared__ float vM[BY + 2][BX + 2];

    int b = blockIdx.z;
    int tileX = blockIdx.x * BX, tileY = blockIdx.y * BY;
    int gx0 = tileX - 3, gy0 = tileY - 3;
    int tid = threadIdx.y * BX + threadIdx.x;
    const float* imF = &g_pool[0][b][0][0];
    const float* imM = &g_pool[1][b][0][0];

    for (int s = tid; s < (BY + 6) * (BX + 6); s += 512) {
        int sy = s / (BX + 6), sx = s % (BX + 6);
        int gy = clampi(gy0 + sy, 0, HP - 1);
        int gx = clampi(gx0 + sx, 0, HP - 1);
        sF[sy][sx] = imF[gy * HP + gx];
        sM[sy][sx] = imM[gy * HP + gx];
    }
    __syncthreads();

    // variance_pre at pixel + 1 halo. Reference quirk: patch-mean taps are
    // img[clamp(u-2+s)] for s in {0,1,2}  (box centered at u-1).
    for (int s = tid; s < (BY + 2) * (BX + 2); s += 512) {
        int sy = s / (BX + 2), sx = s % (BX + 2);
        int uc = clampi(tileY - 1 + sy, 0, HP - 1);
        int vc = clampi(tileX - 1 + sx, 0, HP - 1);
        float pmF = 0.f, pmM = 0.f;
        #pragma unroll
        for (int a = 0; a < 3; a++) {
            int rr = clampi(uc - 2 + a, 0, HP - 1) - gy0;
            #pragma unroll
            for (int bb = 0; bb < 3; bb++) {
                int cc = clampi(vc - 2 + bb, 0, HP - 1) - gx0;
                pmF += sF[rr][cc];
                pmM += sM[rr][cc];
            }
        }
        float cF = sF[uc - gy0][vc - gx0];
        float cM = sM[uc - gy0][vc - gx0];
        float dF = cF - pmF * (1.0f / 9.0f);
        float dM = cM - pmM * (1.0f / 9.0f);
        vF[sy][sx] = dF * dF;
        vM[sy][sx] = dM * dM;
    }
    __syncthreads();

    int y = tileY + threadIdx.y;
    int x = tileX + threadIdx.x;

    float vsF = 0.f, vsM = 0.f;
    #pragma unroll
    for (int a = -1; a <= 1; a++) {
        int rr = clampi(y + a, 0, HP - 1) - (tileY - 1);
        #pragma unroll
        for (int bb = -1; bb <= 1; bb++) {
            int cc = clampi(x + bb, 0, HP - 1) - (tileX - 1);
            vsF += vF[rr][cc];
            vsM += vM[rr][cc];
        }
    }
    float varF = fmaxf(vsF * (1.0f / 9.0f), 1e-4f);
    float varM = fmaxf(vsM * (1.0f / 9.0f), 1e-4f);
    float invF = 1.0f / (varF * 2.0f + 1e-6f);
    float invM = 1.0f / (varM * 2.0f + 1e-6f);
    float cF = sF[y - gy0][x - gx0];
    float cM = sM[y - gy0][x - gx0];

    const int offdx[8] = {-2, -2, -2, 0, 0, 2, 2, 2};
    const int offdy[8] = {-2, 0, 2, -2, 2, -2, 0, 2};
    float eF[8], eM[8];
    float sumF = 0.f, sumM = 0.f;
    #pragma unroll
    for (int c = 0; c < 8; c++) {
        int rr = clampi(y + offdy[c], 0, HP - 1) - gy0;
        int cc = clampi(x + offdx[c], 0, HP - 1) - gx0;
        float oF = sF[rr][cc], oM = sM[rr][cc];
        float dfF = cF - oF, dfM = cM - oM;
        float qF = fminf(dfF * dfF * invF, 50.0f);
        float qM = fminf(dfM * dfM * invM, 50.0f);
        eF[c] = __expf(-qF);
        eM[c] = __expf(-qM);
        sumF += eF[c];
        sumM += eM[c];
    }
    float rF = 1.0f / (sumF + 1e-8f), rM = 1.0f / (sumM + 1e-8f);
    #pragma unroll
    for (int c = 0; c < 8; c++) {
        g_diff[b * 8 + c][y][x] = eF[c] * rF - eM[c] * rM;
    }
}

// ------ bilinear upsample (align corners) of diff, |.| partial sums ------
// Separable: phase 1 x-upsamples needed input rows into smem (each texel read
// once), phase 2 is coalesced LDS + fma + abs. One block per (plane, 32-row strip).
#define UP_ROWS 32
__global__ __launch_bounds__(512) void k_up() {
    const float SCALE = 255.0f / 511.0f;
    __shared__ float xup[18][512];
    __shared__ float red[512];

    int plane = blockIdx.x >> 4;
    int strip = blockIdx.x & 15;
    int yo0 = strip * UP_ROWS;

    int rlo = clampi((int)floorf((float)yo0 * SCALE), 0, HP - 2);
    int rhi = clampi((int)floorf((float)(yo0 + UP_ROWS - 1) * SCALE), 0, HP - 2) + 1;
    int nrows = rhi - rlo + 1;

    // phase 1: x-upsample rows rlo..rhi into smem. thread t owns column t.
    int t = threadIdx.x;
    float px = (float)t * SCALE;
    int j0 = clampi((int)floorf(px), 0, HP - 2);
    float fx = px - (float)j0;
    const float* base = &g_diff[plane][0][0];
    for (int r = 0; r < nrows; r++) {
        const float* row = base + (rlo + r) * HP;
        xup[r][t] = row[j0] * (1.0f - fx) + row[j0 + 1] * fx;
    }
    __syncthreads();

    // phase 2: y-interp, abs, accumulate. thread t owns output column t.
    float acc = 0.f;
    #pragma unroll
    for (int l = 0; l < UP_ROWS; l++) {
        float pos = (float)(yo0 + l) * SCALE;
        int i0 = clampi((int)floorf(pos), 0, HP - 2);
        float fy = pos - (float)i0;
        float v0 = xup[i0 - rlo][t];
        float v1 = xup[i0 - rlo + 1][t];
        acc += fabsf(v0 * (1.0f - fy) + v1 * fy);
    }
    red[t] = acc;
    __syncthreads();
    #pragma unroll
    for (int s = 256; s > 0; s >>= 1) {
        if (t < s) red[t] += red[t + s];
        __syncthreads();
    }
    if (t == 0) g_part_mind[blockIdx.x] = red[0];
}

// ---------------- regularizer: sobel + laplacian on pooled flow ----------------
__global__ __launch_bounds__(256) void k_reg() {
    int idx = blockIdx.x * 256 + threadIdx.x;
    int x = idx & 255, y = (idx >> 8) & 255, b = idx >> 16;
    const float* u = &g_pool[2][b][0][0];
    const float* v = &g_pool[3][b][0][0];
    int ym = max(y - 1, 0), yp = min(y + 1, 255);
    int xm = max(x - 1, 0), xp = min(x + 1, 255);

    float u00 = u[ym * 256 + xm], u01 = u[ym * 256 + x], u02 = u[ym * 256 + xp];
    float u10 = u[y * 256 + xm],  u11 = u[y * 256 + x],  u12 = u[y * 256 + xp];
    float u20 = u[yp * 256 + xm], u21 = u[yp * 256 + x], u22 = u[yp * 256 + xp];
    float v00 = v[ym * 256 + xm], v01 = v[ym * 256 + x], v02 = v[ym * 256 + xp];
    float v10 = v[y * 256 + xm],  v11 = v[y * 256 + x],  v12 = v[y * 256 + xp];
    float v20 = v[yp * 256 + xm], v21 = v[yp * 256 + x], v22 = v[yp * 256 + xp];

    float gxu = (u02 + 2.f * u12 + u22) - (u00 + 2.f * u10 + u20);
    float gyu = (u20 + 2.f * u21 + u22) - (u00 + 2.f * u01 + u02);
    float lpu = u01 + u10 + u12 + u21 - 4.f * u11;
    float gxv = (v02 + 2.f * v12 + v22) - (v00 + 2.f * v10 + v20);
    float gyv = (v20 + 2.f * v21 + v22) - (v00 + 2.f * v01 + v02);
    float lpv = v01 + v10 + v12 + v21 - 4.f * v11;

    float gm = gxu * gxu + gyu * gyu + gxv * gxv + gyv * gyv;
    float lm = lpu * lpu + lpv * lpv;
    float val = fminf(gm, 100.0f) + fminf(lm, 100.0f);

    __shared__ float red[256];
    red[threadIdx.x] = val;
    __syncthreads();
    #pragma unroll
    for (int s = 128; s > 0; s >>= 1) {
        if (threadIdx.x < s) red[threadIdx.x] += red[threadIdx.x + s];
        __syncthreads();
    }
    if (threadIdx.x == 0) g_part_reg[blockIdx.x] = red[0];
}

// -------- fused epilogue: reduce mind + reg partials, MI/NMI, combine --------
__global__ __launch_bounds__(1024) void k_final(float* __restrict__ out) {
    int t = threadIdx.x;
    __shared__ float red[1024];
    __shared__ float s_mind, s_reg, s_nmi;
    __shared__ float hp[256];
    __shared__ float xh[16], yh[16];

    // mind partials (1024)
    red[t] = g_part_mind[t];
    __syncthreads();
    #pragma unroll
    for (int s = 512; s > 0; s >>= 1) {
        if (t < s) red[t] += red[t + s];
        __syncthreads();
    }
    if (t == 0) s_mind = red[0];
    __syncthreads();

    // reg partials (2048)
    red[t] = g_part_reg[t] + g_part_reg[t + 1024];
    __syncthreads();
    #pragma unroll
    for (int s = 512; s > 0; s >>= 1) {
        if (t < s) red[t] += red[t + s];
        __syncthreads();
    }
    if (t == 0) { s_reg = red[0]; s_nmi = 0.f; }
    __syncthreads();

    // MI / NMI per batch (256 active threads)
    for (int b = 0; b < BATCH; b++) {
        float p = 0.f;
        if (t < 256) {
            p = (float)g_hist[b][t] * (1.0f / 65536.0f);
            hp[t] = p;
        }
        __syncthreads();
        if (t < 16) {
            float s = 0.f;
            for (int j = 0; j < 16; j++) s += hp[t * 16 + j];
            xh[t] = s + 1e-5f;
            float s2 = 0.f;
            for (int i2 = 0; i2 < 16; i2++) s2 += hp[i2 * 16 + t];
            yh[t] = s2 + 1e-5f;
        }
        __syncthreads();
        if (t < 256) {
            float hpe = p + 1e-5f;
            red[t] = hpe * (logf(hpe) - logf(xh[t >> 4] * yh[t & 15]));
        }
        __syncthreads();
        #pragma unroll
        for (int s = 128; s > 0; s >>= 1) {
            if (t < s) red[t] += red[t + s];
            __syncthreads();
        }
        if (t == 0) {
            float mi = red[0];
            float hx = 0.f, hy = 0.f;
            for (int k = 0; k < 16; k++) {
                hx -= xh[k] * logf(xh[k]);
                hy -= yh[k] * logf(yh[k]);
            }
            float se = hx + hy;
            float nmi = (se < 1e-10f) ? 0.0f : 2.0f * mi / se;
            s_nmi += fminf(fmaxf(nmi, -1.0f), 1.0f);
        }
        __syncthreads();
    }

    if (t == 0) {
        float m = s_nmi * (1.0f / BATCH);
        m = fminf(fmaxf(m, -1.0f), 1.0f);
        out[0] = -m
               + 5.0f * (s_mind * (1.0f / 16777216.0f))
               + 0.1f * (s_reg * (1.0f / 524288.0f));
    }
}

// ---------------- launch ----------------
extern "C" void kernel_launch(void* const* d_in, const int* in_sizes, int n_in,
                              void* d_out, int out_size) {
    const float* fixed = (const float*)d_in[0];
    const float* moved = (const float*)d_in[1];
    const float* flow  = (const float*)d_in[2];
    if (n_in >= 3) {
        int fi = -1;
        for (int i = 0; i < 3; i++) if (in_sizes[i] == 2 * BATCH * HF * HF) fi = i;
        if (fi == 0) { flow = (const float*)d_in[0]; fixed = (const float*)d_in[1]; moved = (const float*)d_in[2]; }
        else if (fi == 1) { fixed = (const float*)d_in[0]; flow = (const float*)d_in[1]; moved = (const float*)d_in[2]; }
    }

    k_zero<<<8, 256>>>();
    k_pool<<<512, 256>>>(fixed, moved, flow);
    k_reg<<<2048, 256>>>();
    k_mind<<<dim3(HP / BX, HP / BY, BATCH), dim3(BX, BY)>>>();
    k_up<<<1024, 512>>>();
    k_final<<<1, 1024>>>((float*)d_out);
}